// round 1
// baseline (speedup 1.0000x reference)
#include <cuda_runtime.h>

// Problem constants (fixed by the reference):
//   V=50000, D=256, S=128, B=64
// Inputs (metadata order):
//   d_in[0] questions  int32 [B,S]
//   d_in[1] q_position f32   [B,S]
//   d_in[2] word_emb   f32   [V,D]
//   d_in[3] cmp_emb    f32   [V,D]
//   d_in[4] weighted_q f32   [S]
// Output: float32, concat(real[B,D,D], imag[B,D,D]) = 8388608 elements.
//
// Math (per batch):
//   R[s,d] = word_emb[q[s],d]
//   I[s,d] = cmp_emb[q[s],d] * pos[s]
//   real[d,e] = sum_s R[s,d]*(w[s]*R[s,e]) + I[s,d]*(w[s]*I[s,e])
//   imag[d,e] = sum_s I[s,d]*(w[s]*R[s,e]) - R[s,d]*(w[s]*I[s,e])
//
// Kernel: fused gather + 4-way weighted Gram GEMM, fp32 via packed
// fma.rn.f32x2 (FFMA2: 2 FMA lanes/inst — 3-reg FFMA is half-rate on sm_103a).
// CTA tile 128(d) x 64(e), per-thread 4d x 8e (4 f32x2 pairs along e).
// Minus sign for imag folded into a pre-negated SMEM copy of w*I.

#define S_LEN 128
#define D_DIM 256
#define B_DIM 64
#define KC    32   // k-chunk rows resident in SMEM

// dyn smem: aR[KC][128] aI[KC][128] bR[KC][64] bI[KC][64] bIn[KC][64]
#define SMEM_FLOATS (KC * (128 + 128 + 64 + 64 + 64))
#define SMEM_BYTES  (SMEM_FLOATS * 4)

__device__ __forceinline__ unsigned long long pack2(float x) {
    unsigned long long r;
    unsigned int u = __float_as_uint(x);
    asm("mov.b64 %0, {%1, %1};" : "=l"(r) : "r"(u));
    return r;
}

__device__ __forceinline__ void fma2(unsigned long long& d,
                                     unsigned long long a,
                                     unsigned long long b) {
    asm("fma.rn.f32x2 %0, %1, %2, %0;" : "+l"(d) : "l"(a), "l"(b));
}

__device__ __forceinline__ float2 unpack2(unsigned long long v) {
    float2 r;
    asm("mov.b64 {%0, %1}, %2;" : "=f"(r.x), "=f"(r.y) : "l"(v));
    return r;
}

__global__ void __launch_bounds__(256, 2)
cmp_density_kernel(const int*   __restrict__ questions,
                   const float* __restrict__ qpos,
                   const float* __restrict__ wemb,
                   const float* __restrict__ cemb,
                   const float* __restrict__ wq,
                   float*       __restrict__ out)
{
    extern __shared__ float sm[];
    float* aR  = sm;                 // [KC][128]  R, d-columns
    float* aI  = aR  + KC * 128;     // [KC][128]  I, d-columns
    float* bR  = aI  + KC * 128;     // [KC][64]   w*R, e-columns
    float* bI  = bR  + KC * 64;      // [KC][64]   w*I, e-columns
    float* bIn = bI  + KC * 64;      // [KC][64]  -w*I, e-columns

    __shared__ int   sq[S_LEN];
    __shared__ float sp[S_LEN];
    __shared__ float sw[S_LEN];

    const int tid = threadIdx.x;
    const int et  = blockIdx.x;   // 0..3   e tile (64 wide)
    const int dt  = blockIdx.y;   // 0..1   d tile (128 wide)
    const int b   = blockIdx.z;   // 0..63

    if (tid < S_LEN) {
        sq[tid] = questions[b * S_LEN + tid];
        sp[tid] = qpos[b * S_LEN + tid];
        sw[tid] = wq[tid];
    }
    __syncthreads();

    const int eg = tid & 7;    // e group: 8 cols each
    const int dg = tid >> 3;   // d group: 4 rows each (0..31)

    unsigned long long accRe[4][4];
    unsigned long long accIm[4][4];
#pragma unroll
    for (int i = 0; i < 4; i++)
#pragma unroll
        for (int j = 0; j < 4; j++) { accRe[i][j] = 0ull; accIm[i][j] = 0ull; }

    for (int k0 = 0; k0 < S_LEN; k0 += KC) {
        // ---- gather a-side (d columns): KC*32 float4 per array ----
#pragma unroll
        for (int it = 0; it < (KC * 32) / 256; ++it) {
            int idx = tid + it * 256;
            int s   = idx >> 5;        // 0..KC-1
            int c4  = idx & 31;        // float4 index over 128 floats
            int q   = sq[k0 + s];
            float p = sp[k0 + s];
            const float4* wr = (const float4*)(wemb + (size_t)q * D_DIM + dt * 128);
            const float4* cr = (const float4*)(cemb + (size_t)q * D_DIM + dt * 128);
            float4 r4 = wr[c4];
            float4 c4v = cr[c4];
            ((float4*)(aR + s * 128))[c4] = r4;
            ((float4*)(aI + s * 128))[c4] =
                make_float4(c4v.x * p, c4v.y * p, c4v.z * p, c4v.w * p);
        }
        // ---- gather b-side (e columns, w-scaled): KC*16 float4 per array ----
#pragma unroll
        for (int it = 0; it < (KC * 16) / 256; ++it) {
            int idx = tid + it * 256;
            int s   = idx >> 4;        // 0..KC-1
            int c4  = idx & 15;        // float4 index over 64 floats
            int q   = sq[k0 + s];
            float p = sp[k0 + s];
            float w = sw[k0 + s];
            const float4* wr = (const float4*)(wemb + (size_t)q * D_DIM + et * 64);
            const float4* cr = (const float4*)(cemb + (size_t)q * D_DIM + et * 64);
            float4 r4  = wr[c4];
            float4 c4v = cr[c4];
            float wp = w * p;
            float4 br4 = make_float4(r4.x * w,  r4.y * w,  r4.z * w,  r4.w * w);
            float4 bi4 = make_float4(c4v.x * wp, c4v.y * wp, c4v.z * wp, c4v.w * wp);
            ((float4*)(bR  + s * 64))[c4] = br4;
            ((float4*)(bI  + s * 64))[c4] = bi4;
            ((float4*)(bIn + s * 64))[c4] =
                make_float4(-bi4.x, -bi4.y, -bi4.z, -bi4.w);
        }
        __syncthreads();

        // ---- compute over this k-chunk ----
        for (int k = 0; k < KC; ++k) {
            float4 ar = *(const float4*)(aR + k * 128 + dg * 4);
            float4 ai = *(const float4*)(aI + k * 128 + dg * 4);

            const float* bRk = bR  + k * 64 + eg * 8;
            const float* bIk = bI  + k * 64 + eg * 8;
            const float* bNk = bIn + k * 64 + eg * 8;

            unsigned long long bRv[4], bIv[4], bNv[4];
            {
                ulonglong2 t;
                t = *(const ulonglong2*)(bRk);     bRv[0] = t.x; bRv[1] = t.y;
                t = *(const ulonglong2*)(bRk + 4); bRv[2] = t.x; bRv[3] = t.y;
                t = *(const ulonglong2*)(bIk);     bIv[0] = t.x; bIv[1] = t.y;
                t = *(const ulonglong2*)(bIk + 4); bIv[2] = t.x; bIv[3] = t.y;
                t = *(const ulonglong2*)(bNk);     bNv[0] = t.x; bNv[1] = t.y;
                t = *(const ulonglong2*)(bNk + 4); bNv[2] = t.x; bNv[3] = t.y;
            }

            unsigned long long aRp[4], aIp[4];
            aRp[0] = pack2(ar.x); aRp[1] = pack2(ar.y);
            aRp[2] = pack2(ar.z); aRp[3] = pack2(ar.w);
            aIp[0] = pack2(ai.x); aIp[1] = pack2(ai.y);
            aIp[2] = pack2(ai.z); aIp[3] = pack2(ai.w);

#pragma unroll
            for (int d = 0; d < 4; d++) {
#pragma unroll
                for (int p = 0; p < 4; p++) {
                    fma2(accRe[d][p], aRp[d], bRv[p]);   // R_d * wR_e
                    fma2(accRe[d][p], aIp[d], bIv[p]);   // I_d * wI_e
                    fma2(accIm[d][p], aIp[d], bRv[p]);   // I_d * wR_e
                    fma2(accIm[d][p], aRp[d], bNv[p]);   // R_d * (-wI_e)
                }
            }
        }
        __syncthreads();
    }

    // ---- epilogue: coalesced float4 stores ----
    const int d0 = dt * 128 + dg * 4;
    const int e0 = et * 64 + eg * 8;
    float* oRe = out + (size_t)b * D_DIM * D_DIM;
    float* oIm = oRe + (size_t)B_DIM * D_DIM * D_DIM;

#pragma unroll
    for (int d = 0; d < 4; d++) {
        float2 r0 = unpack2(accRe[d][0]);
        float2 r1 = unpack2(accRe[d][1]);
        float2 r2 = unpack2(accRe[d][2]);
        float2 r3 = unpack2(accRe[d][3]);
        float2 m0 = unpack2(accIm[d][0]);
        float2 m1 = unpack2(accIm[d][1]);
        float2 m2 = unpack2(accIm[d][2]);
        float2 m3 = unpack2(accIm[d][3]);

        size_t row = (size_t)(d0 + d) * D_DIM + e0;
        *(float4*)(oRe + row)     = make_float4(r0.x, r0.y, r1.x, r1.y);
        *(float4*)(oRe + row + 4) = make_float4(r2.x, r2.y, r3.x, r3.y);
        *(float4*)(oIm + row)     = make_float4(m0.x, m0.y, m1.x, m1.y);
        *(float4*)(oIm + row + 4) = make_float4(m2.x, m2.y, m3.x, m3.y);
    }
}

extern "C" void kernel_launch(void* const* d_in, const int* in_sizes, int n_in,
                              void* d_out, int out_size) {
    const int*   questions = (const int*)d_in[0];
    const float* qpos      = (const float*)d_in[1];
    const float* wemb      = (const float*)d_in[2];
    const float* cemb      = (const float*)d_in[3];
    const float* wq        = (const float*)d_in[4];
    float*       out       = (float*)d_out;

    cudaFuncSetAttribute(cmp_density_kernel,
                         cudaFuncAttributeMaxDynamicSharedMemorySize, SMEM_BYTES);

    dim3 grid(4 /*e tiles*/, 2 /*d tiles*/, B_DIM /*batch*/);
    cmp_density_kernel<<<grid, 256, SMEM_BYTES>>>(questions, qpos, wemb, cemb,
                                                  wq, out);
}

// round 3
// speedup vs baseline: 3.3736x; 3.3736x over previous
#include <cuda_runtime.h>
#include <cstdint>

// CMPModel density matrix via warp-level mma.sync tf32 (sm_80+ PTX -> works on
// plain sm_103 target; tcgen05 is rejected by this build's ptxas target).
// V=50000, D=256, S=128, B=64.
//
// Per batch:  R[k,d]=word_emb[q[k],d],  I[k,d]=cmp_emb[q[k],d]*pos[k]
//   real[d,e] = sum_k w[k]( R[k,d]R[k,e] + I[k,d]I[k,e] )
//   imag[d,e] = sum_k w[k]( I[k,d]R[k,e] - R[k,d]I[k,e] )
//
// CTA = (e-half, d-half, batch): 128x128 output tile, BOTH real+imag.
// 512 threads = 16 warps: warps 0-7 real, 8-15 imag; warp tile 64(m=d) x 32(n=e).
// SMEM tiles [k][feature], pad 136 floats: AR=R, AI=I (d-half, MMA "A" via
// frag rows), BR=wR, BI=wI, BN=-wI (e-half).  tf32-rounded at gather.

#define D_DIM 256
#define S_LEN 128
#define B_DIM 64
#define KC    32
#define PAD   136                      // floats per k-row (conflict-free frags)

#define TILE_FLOATS (KC * PAD)         // 4352
#define SMEM_FLOATS (5 * TILE_FLOATS)
#define SMEM_BYTES  (SMEM_FLOATS * 4)  // 87040 B

__device__ __forceinline__ uint32_t tf32r(float f) {
    uint32_t r;
    asm("cvt.rna.tf32.f32 %0, %1;" : "=r"(r) : "f"(f));
    return r;
}

__device__ __forceinline__ void mma8(float* c, const uint32_t* a, const uint32_t* b) {
    asm volatile(
        "mma.sync.aligned.m16n8k8.row.col.f32.tf32.tf32.f32 "
        "{%0,%1,%2,%3}, {%4,%5,%6,%7}, {%8,%9}, {%0,%1,%2,%3};"
        : "+f"(c[0]), "+f"(c[1]), "+f"(c[2]), "+f"(c[3])
        : "r"(a[0]), "r"(a[1]), "r"(a[2]), "r"(a[3]), "r"(b[0]), "r"(b[1]));
}

__global__ void __launch_bounds__(512, 1)
cmp_mma_kernel(const int*   __restrict__ questions,
               const float* __restrict__ qpos,
               const float* __restrict__ wemb,
               const float* __restrict__ cemb,
               const float* __restrict__ wq,
               float*       __restrict__ out)
{
    extern __shared__ float sm[];
    float* AR = sm;                    // [KC][PAD]  R   (d-half features)
    float* AI = sm + 1 * TILE_FLOATS;  // [KC][PAD]  I
    float* BR = sm + 2 * TILE_FLOATS;  // [KC][PAD]  wR  (e-half features)
    float* BI = sm + 3 * TILE_FLOATS;  // [KC][PAD]  wI
    float* BN = sm + 4 * TILE_FLOATS;  // [KC][PAD] -wI

    __shared__ int   sq[S_LEN];
    __shared__ float sp[S_LEN];
    __shared__ float sw[S_LEN];

    const int tid  = threadIdx.x;
    const int wid  = tid >> 5;
    const int lane = tid & 31;
    const int et   = blockIdx.x;   // e-half 0/1
    const int dt   = blockIdx.y;   // d-half 0/1
    const int b    = blockIdx.z;

    if (tid < S_LEN) {
        sq[tid] = questions[b * S_LEN + tid];
        sp[tid] = qpos[b * S_LEN + tid];
        sw[tid] = wq[tid];
    }
    __syncthreads();

    // compute-warp mapping
    const int wg = wid >> 3;       // 0: real, 1: imag
    const int w8 = wid & 7;
    const int mr = w8 >> 2;        // warp m block (64 rows)
    const int nc = w8 & 3;         // warp n block (32 cols)

    float acc[4][4][4];
#pragma unroll
    for (int i = 0; i < 4; i++)
#pragma unroll
        for (int j = 0; j < 4; j++)
#pragma unroll
            for (int q = 0; q < 4; q++) acc[i][j][q] = 0.f;

    // gather lane decode: 8 lanes of consecutive f4 (128B LDG), 4 k per warp
    const int f4l = lane & 7;
    const int k4  = lane >> 3;

    const int r = lane >> 2;       // frag row/col helpers
    const int c = lane & 3;

    for (int g = 0; g < 4; ++g) {
        __syncthreads();   // previous compute done before overwrite

        // ---------- gather k-chunk g into SMEM ----------
#pragma unroll
        for (int i = 0; i < 4; ++i) {
            const int witer = wid + 16 * i;        // 0..63, each task once
            const int half  = witer >> 5;          // 0: d-side (A), 1: e-side (B)
            const int u     = witer & 31;
            const int k     = (u & 7) * 4 + k4;    // 0..31
            const int f4    = (u >> 3) * 8 + f4l;  // 0..31

            const int   s  = g * KC + k;
            const int   q  = sq[s];
            const float pp = sp[s];
            const int   fofs = (half ? et : dt) * 128 + f4 * 4;
            const float4 rv = *(const float4*)(wemb + (size_t)q * D_DIM + fofs);
            const float4 cv = *(const float4*)(cemb + (size_t)q * D_DIM + fofs);
            const float ix = cv.x * pp, iy = cv.y * pp, iz = cv.z * pp, iw = cv.w * pp;
            const int dst = k * PAD + f4 * 4;

            if (half == 0) {
                *(uint4*)(AR + dst) = make_uint4(tf32r(rv.x), tf32r(rv.y),
                                                 tf32r(rv.z), tf32r(rv.w));
                *(uint4*)(AI + dst) = make_uint4(tf32r(ix), tf32r(iy),
                                                 tf32r(iz), tf32r(iw));
            } else {
                const float ww = sw[s];
                *(uint4*)(BR + dst) = make_uint4(tf32r(rv.x * ww), tf32r(rv.y * ww),
                                                 tf32r(rv.z * ww), tf32r(rv.w * ww));
                uint4 bi = make_uint4(tf32r(ix * ww), tf32r(iy * ww),
                                      tf32r(iz * ww), tf32r(iw * ww));
                *(uint4*)(BI + dst) = bi;
                *(uint4*)(BN + dst) = make_uint4(bi.x ^ 0x80000000u, bi.y ^ 0x80000000u,
                                                 bi.z ^ 0x80000000u, bi.w ^ 0x80000000u);
            }
        }
        __syncthreads();

        // ---------- compute: acc += A1*BR + A2*B2 over KC ----------
        // real: A1=AR (R),  A2=AI (I),  B2=BI (wI)
        // imag: A1=AI (I),  A2=AR (R),  B2=BN (-wI)
        const float* A1 = wg ? AI : AR;
        const float* A2 = wg ? AR : AI;
        const float* B2 = wg ? BN : BI;

#pragma unroll
        for (int ks = 0; ks < 4; ++ks) {
            const int k0 = ks * 8;
            const int rowL = (k0 + c) * PAD;       // frag rows k0+c, k0+4+c
            const int rowH = (k0 + 4 + c) * PAD;

            uint32_t bfr[4][2], bf2[4][2];
#pragma unroll
            for (int nt = 0; nt < 4; ++nt) {
                const int n0 = nc * 32 + nt * 8 + r;
                bfr[nt][0] = __float_as_uint(BR[rowL + n0]);
                bfr[nt][1] = __float_as_uint(BR[rowH + n0]);
                bf2[nt][0] = __float_as_uint(B2[rowL + n0]);
                bf2[nt][1] = __float_as_uint(B2[rowH + n0]);
            }
#pragma unroll
            for (int mt = 0; mt < 4; ++mt) {
                const int m0 = mr * 64 + mt * 16 + r;
                uint32_t a1[4], a2[4];
                a1[0] = __float_as_uint(A1[rowL + m0]);
                a1[1] = __float_as_uint(A1[rowL + m0 + 8]);
                a1[2] = __float_as_uint(A1[rowH + m0]);
                a1[3] = __float_as_uint(A1[rowH + m0 + 8]);
                a2[0] = __float_as_uint(A2[rowL + m0]);
                a2[1] = __float_as_uint(A2[rowL + m0 + 8]);
                a2[2] = __float_as_uint(A2[rowH + m0]);
                a2[3] = __float_as_uint(A2[rowH + m0 + 8]);
#pragma unroll
                for (int nt = 0; nt < 4; ++nt) {
                    mma8(acc[mt][nt], a1, bfr[nt]);
                    mma8(acc[mt][nt], a2, bf2[nt]);
                }
            }
        }
    }

    // ---------- epilogue ----------
    float* ob = out + (wg ? (size_t)B_DIM * D_DIM * D_DIM : (size_t)0)
                    + (size_t)b * D_DIM * D_DIM;
#pragma unroll
    for (int mt = 0; mt < 4; ++mt) {
        const int d = dt * 128 + mr * 64 + mt * 16 + r;
#pragma unroll
        for (int nt = 0; nt < 4; ++nt) {
            const int e = et * 128 + nc * 32 + nt * 8 + 2 * c;
            *(float2*)(ob + (size_t)d * D_DIM + e) =
                make_float2(acc[mt][nt][0], acc[mt][nt][1]);
            *(float2*)(ob + (size_t)(d + 8) * D_DIM + e) =
                make_float2(acc[mt][nt][2], acc[mt][nt][3]);
        }
    }
}

extern "C" void kernel_launch(void* const* d_in, const int* in_sizes, int n_in,
                              void* d_out, int out_size) {
    const int*   questions = (const int*)d_in[0];
    const float* qpos      = (const float*)d_in[1];
    const float* wemb      = (const float*)d_in[2];
    const float* cemb      = (const float*)d_in[3];
    const float* wq        = (const float*)d_in[4];
    float*       out       = (float*)d_out;

    cudaFuncSetAttribute(cmp_mma_kernel,
                         cudaFuncAttributeMaxDynamicSharedMemorySize, SMEM_BYTES);

    dim3 grid(2 /*e-half*/, 2 /*d-half*/, B_DIM);
    cmp_mma_kernel<<<grid, 512, SMEM_BYTES>>>(questions, qpos, wemb, cemb, wq, out);
}

// round 4
// speedup vs baseline: 3.5694x; 1.0580x over previous
#include <cuda_runtime.h>
#include <cstdint>

// CMPModel density matrix via warp-level mma.sync tf32, sm_103.
// V=50000, D=256, S=128, B=64.
//
// R[k,d]=word_emb[q[k],d], I[k,d]=cmp_emb[q[k],d]*pos[k]
//   real[d,e] = sum_k w[k]( R[k,d]R[k,e] + I[k,d]I[k,e] )
//   imag[d,e] = sum_k w[k]( I[k,d]R[k,e] - R[k,d]I[k,e] )
//
// CTA = (e-half, d-half, batch): 128x128 tile of BOTH real and imag.
// 16 warps, each computes real+imag for one 32(d) x 32(e) sub-tile
// (A fragments {R,I} and B fragments {wR,wI} shared between the two
// outputs; the minus sign comes from XOR-negating the wI fragment).
// SMEM: 4 tiles [KC][PAD] per stage, double-buffered; one sync/chunk —
// gather(next stage) issues before compute(current), so LDG latency of
// one warp hides behind MMA issue of the others.

#define D_DIM 256
#define S_LEN 128
#define B_DIM 64
#define KC    32
#define PAD   136

#define TILE_FLOATS (KC * PAD)              // 4352
#define STAGE_FLOATS (4 * TILE_FLOATS)      // AR, AI, BR, BI
#define SMEM_FLOATS (2 * STAGE_FLOATS)
#define SMEM_BYTES  (SMEM_FLOATS * 4)       // 139264 B

__device__ __forceinline__ uint32_t tf32r(float f) {
    uint32_t r;
    asm("cvt.rna.tf32.f32 %0, %1;" : "=r"(r) : "f"(f));
    return r;
}

__device__ __forceinline__ void mma8(float* c, const uint32_t* a, const uint32_t* b) {
    asm volatile(
        "mma.sync.aligned.m16n8k8.row.col.f32.tf32.tf32.f32 "
        "{%0,%1,%2,%3}, {%4,%5,%6,%7}, {%8,%9}, {%0,%1,%2,%3};"
        : "+f"(c[0]), "+f"(c[1]), "+f"(c[2]), "+f"(c[3])
        : "r"(a[0]), "r"(a[1]), "r"(a[2]), "r"(a[3]), "r"(b[0]), "r"(b[1]));
}

__global__ void __launch_bounds__(512, 1)
cmp_mma2_kernel(const int*   __restrict__ questions,
                const float* __restrict__ qpos,
                const float* __restrict__ wemb,
                const float* __restrict__ cemb,
                const float* __restrict__ wq,
                float*       __restrict__ out)
{
    extern __shared__ float sm[];
    __shared__ int   sq[S_LEN];
    __shared__ float sp[S_LEN];
    __shared__ float sw[S_LEN];

    const int tid  = threadIdx.x;
    const int wid  = tid >> 5;
    const int lane = tid & 31;
    const int et   = blockIdx.x;   // e-half 0/1
    const int dt   = blockIdx.y;   // d-half 0/1
    const int b    = blockIdx.z;

    if (tid < S_LEN) {
        sq[tid] = questions[b * S_LEN + tid];
        sp[tid] = qpos[b * S_LEN + tid];
        sw[tid] = wq[tid];
    }
    __syncthreads();

    // warp -> 32x32 sub-tile
    const int mr = wid >> 2;       // d block (32 rows)
    const int nc = wid & 3;        // e block (32 cols)

    float accRe[2][4][4];
    float accIm[2][4][4];
#pragma unroll
    for (int i = 0; i < 2; i++)
#pragma unroll
        for (int j = 0; j < 4; j++)
#pragma unroll
            for (int q = 0; q < 4; q++) { accRe[i][j][q] = 0.f; accIm[i][j][q] = 0.f; }

    // gather lane decode
    const int f4l = lane & 7;      // consecutive float4 -> 128B coalesced
    const int k4  = lane >> 3;

    // fragment lane decode
    const int r = lane >> 2;
    const int c = lane & 3;

    // ---- gather chunk g into stage buffer ----
    auto gather = [&](int g) {
        float* stage = sm + (g & 1) * STAGE_FLOATS;
        float* AR = stage;
        float* AI = stage + 1 * TILE_FLOATS;
        float* BR = stage + 2 * TILE_FLOATS;
        float* BI = stage + 3 * TILE_FLOATS;
#pragma unroll
        for (int i = 0; i < 4; ++i) {
            const int witer = wid + 16 * i;        // 0..63
            const int half  = witer >> 5;          // 0: d-side, 1: e-side
            const int u     = witer & 31;
            const int k     = (u & 7) * 4 + k4;
            const int f4    = (u >> 3) * 8 + f4l;

            const int   s  = g * KC + k;
            const int   q  = sq[s];
            const float pp = sp[s];
            const int   fofs = (half ? et : dt) * 128 + f4 * 4;
            const float4 rv = *(const float4*)(wemb + (size_t)q * D_DIM + fofs);
            const float4 cv = *(const float4*)(cemb + (size_t)q * D_DIM + fofs);
            const float ix = cv.x * pp, iy = cv.y * pp, iz = cv.z * pp, iw = cv.w * pp;
            const int dst = k * PAD + f4 * 4;

            if (half == 0) {
                *(uint4*)(AR + dst) = make_uint4(tf32r(rv.x), tf32r(rv.y),
                                                 tf32r(rv.z), tf32r(rv.w));
                *(uint4*)(AI + dst) = make_uint4(tf32r(ix), tf32r(iy),
                                                 tf32r(iz), tf32r(iw));
            } else {
                const float ww = sw[s];
                *(uint4*)(BR + dst) = make_uint4(tf32r(rv.x * ww), tf32r(rv.y * ww),
                                                 tf32r(rv.z * ww), tf32r(rv.w * ww));
                *(uint4*)(BI + dst) = make_uint4(tf32r(ix * ww), tf32r(iy * ww),
                                                 tf32r(iz * ww), tf32r(iw * ww));
            }
        }
    };

    gather(0);
    __syncthreads();

    for (int g = 0; g < 4; ++g) {
        float* stage = sm + (g & 1) * STAGE_FLOATS;
        const float* AR = stage;
        const float* AI = stage + 1 * TILE_FLOATS;
        const float* BR = stage + 2 * TILE_FLOATS;
        const float* BI = stage + 3 * TILE_FLOATS;

        if (g < 3) gather(g + 1);   // into other stage; overlaps compute below

#pragma unroll
        for (int ks = 0; ks < 4; ++ks) {
            const int k0 = ks * 8;
            const int rowL = (k0 + c) * PAD;
            const int rowH = (k0 + 4 + c) * PAD;

            uint32_t bR[4][2], bI[4][2], bN[4][2];
#pragma unroll
            for (int nt = 0; nt < 4; ++nt) {
                const int n0 = nc * 32 + nt * 8 + r;
                bR[nt][0] = __float_as_uint(BR[rowL + n0]);
                bR[nt][1] = __float_as_uint(BR[rowH + n0]);
                bI[nt][0] = __float_as_uint(BI[rowL + n0]);
                bI[nt][1] = __float_as_uint(BI[rowH + n0]);
                bN[nt][0] = bI[nt][0] ^ 0x80000000u;
                bN[nt][1] = bI[nt][1] ^ 0x80000000u;
            }
#pragma unroll
            for (int mt = 0; mt < 2; ++mt) {
                const int m0 = mr * 32 + mt * 16 + r;
                uint32_t aR[4], aI[4];
                aR[0] = __float_as_uint(AR[rowL + m0]);
                aR[1] = __float_as_uint(AR[rowL + m0 + 8]);
                aR[2] = __float_as_uint(AR[rowH + m0]);
                aR[3] = __float_as_uint(AR[rowH + m0 + 8]);
                aI[0] = __float_as_uint(AI[rowL + m0]);
                aI[1] = __float_as_uint(AI[rowL + m0 + 8]);
                aI[2] = __float_as_uint(AI[rowH + m0]);
                aI[3] = __float_as_uint(AI[rowH + m0 + 8]);
#pragma unroll
                for (int nt = 0; nt < 4; ++nt) {
                    mma8(accRe[mt][nt], aR, bR[nt]);   // R  * wR
                    mma8(accRe[mt][nt], aI, bI[nt]);   // I  * wI
                    mma8(accIm[mt][nt], aI, bR[nt]);   // I  * wR
                    mma8(accIm[mt][nt], aR, bN[nt]);   // R  * -wI
                }
            }
        }
        __syncthreads();
    }

    // ---- epilogue: real then imag, float2 stores ----
    float* oRe = out + (size_t)b * D_DIM * D_DIM;
    float* oIm = oRe + (size_t)B_DIM * D_DIM * D_DIM;
#pragma unroll
    for (int mt = 0; mt < 2; ++mt) {
        const int d = dt * 128 + mr * 32 + mt * 16 + r;
#pragma unroll
        for (int nt = 0; nt < 4; ++nt) {
            const int e = et * 128 + nc * 32 + nt * 8 + 2 * c;
            *(float2*)(oRe + (size_t)d * D_DIM + e) =
                make_float2(accRe[mt][nt][0], accRe[mt][nt][1]);
            *(float2*)(oRe + (size_t)(d + 8) * D_DIM + e) =
                make_float2(accRe[mt][nt][2], accRe[mt][nt][3]);
            *(float2*)(oIm + (size_t)d * D_DIM + e) =
                make_float2(accIm[mt][nt][0], accIm[mt][nt][1]);
            *(float2*)(oIm + (size_t)(d + 8) * D_DIM + e) =
                make_float2(accIm[mt][nt][2], accIm[mt][nt][3]);
        }
    }
}

extern "C" void kernel_launch(void* const* d_in, const int* in_sizes, int n_in,
                              void* d_out, int out_size) {
    const int*   questions = (const int*)d_in[0];
    const float* qpos      = (const float*)d_in[1];
    const float* wemb      = (const float*)d_in[2];
    const float* cemb      = (const float*)d_in[3];
    const float* wq        = (const float*)d_in[4];
    float*       out       = (float*)d_out;

    cudaFuncSetAttribute(cmp_mma2_kernel,
                         cudaFuncAttributeMaxDynamicSharedMemorySize, SMEM_BYTES);

    dim3 grid(2 /*e-half*/, 2 /*d-half*/, B_DIM);
    cmp_mma2_kernel<<<grid, 512, SMEM_BYTES>>>(questions, qpos, wemb, cemb, wq, out);
}